// round 14
// baseline (speedup 1.0000x reference)
#include <cuda_runtime.h>
#include <cuda_bf16.h>
#include <math.h>
#include <stdint.h>

// Problem constants
#define TT 256      // T
#define BBATCH 64   // B
#define EE 512      // E (= input dim for ALL layers, since 2H = 512)
#define HH 256      // H
#define G4 1024     // 4H
#define HD2 512     // 2H
#define NTAGS 6
#define TAG_START 4
#define TAG_STOP 5
#define NEGV -1000000.0f

typedef unsigned long long ull;

// ---------------- device scratch (static allocations only) ----------------
__device__ float g_x[(size_t)TT * BBATCH * EE];            // zbuf (attention)
__device__ float g_y[(size_t)TT * BBATCH * EE];            // fp32 lstm_out (layer 2)
__device__ float g_pre[(size_t)TT * BBATCH * 2048];        // (t,b,[dir0 1024 | dir1 1024])
__device__ float g_hb[2 * 2 * 8 * 2048];                   // [parity][dir][bg][u*8+b] h-state
__device__ float g_bias[3 * 2 * G4];                       // b_ih + b_hh combined
__device__ float g_wt[(size_t)3 * 2 * 8 * 32768];          // w_hh re-tiled per (l,d,ugi,u_in,kq,kk,g)
__device__ float g_energy[(size_t)TT * BBATCH];            // energy then softmax weights
__device__ float g_feats[(size_t)BBATCH * TT * NTAGS];     // [b][t][tag]
__device__ unsigned int g_flag2[128];                      // [d*64 + bg*8 + ugi] monotonic step flags
// bf16 buffers for tensor-core GEMM (A produced by embed / LSTM)
__device__ __nv_bfloat16 g_ah[(size_t)TT * BBATCH * EE];   // A (bf16)
#define WSPLIT_N (3 * 2 * G4 * EE + 512 * 512)             // w_ih (all) + aw1
__device__ __nv_bfloat16 g_wh2[WSPLIT_N];

// ---------------- f32x2 packed-FMA helpers ----------------
__device__ __forceinline__ void ffma2(ull& d, ull a, ull b) {
    asm("fma.rn.f32x2 %0, %1, %2, %0;" : "+l"(d) : "l"(a), "l"(b));
}
__device__ __forceinline__ ull addx2(ull a, ull b) {
    ull r;
    asm("add.rn.f32x2 %0, %1, %2;" : "=l"(r) : "l"(a), "l"(b));
    return r;
}
__device__ __forceinline__ ull pack2(float x, float y) {
    ull r;
    asm("mov.b64 %0, {%1, %2};" : "=l"(r) : "f"(x), "f"(y));
    return r;
}
__device__ __forceinline__ void unpack2(float& x, float& y, ull v) {
    asm("mov.b64 {%0, %1}, %2;" : "=f"(x), "=f"(y) : "l"(v));
}

// ---------------- cp.async helpers ----------------
#define CP_ASYNC16(dst, src) \
    asm volatile("cp.async.cg.shared.global [%0], [%1], 16;" :: "r"(dst), "l"(src))
#define CP_COMMIT() asm volatile("cp.async.commit_group;" ::: "memory")
#define CP_WAIT(n) asm volatile("cp.async.wait_group %0;" :: "n"(n) : "memory")

// ---------------- tiny utility kernels ----------------
__global__ void zero_out_kernel(float* out) { out[0] = 0.f; }

__global__ void bias_kernel(const float* __restrict__ b_ih, const float* __restrict__ b_hh) {
    int i = blockIdx.x * blockDim.x + threadIdx.x;
    if (i < 3 * 2 * G4) g_bias[i] = b_ih[i] + b_hh[i];
}

__global__ void zero_state_kernel() {
    int i = blockIdx.x * blockDim.x + threadIdx.x;
    if (i < 2 * 2 * 8 * 2048) g_hb[i] = 0.f;
    if (i < 128) g_flag2[i] = 0u;
}

// Re-tile w_hh (3,2,1024,256) into g_wt[l][d][ugi][u_in][kq][kk][g]
__global__ void wt_kernel(const float* __restrict__ whh) {
    size_t i = (size_t)blockIdx.x * blockDim.x + threadIdx.x;
    const size_t n = (size_t)3 * 2 * 8 * 32768;
    if (i >= n) return;
    int g    = i & 3;
    int kk   = (i >> 2) & 31;
    int kq   = (i >> 7) & 7;
    int u_in = (i >> 10) & 31;
    int ugi  = (i >> 15) & 7;
    int ld   = (int)(i >> 18);
    int u = ugi * 32 + u_in;
    int k = kq * 32 + kk;
    g_wt[i] = whh[((size_t)ld * G4 + g * 256 + u) * HH + k];
}

// gather embeddings -> g_ah[t][b][e] (bf16)
__global__ void embed_kernel(const int* __restrict__ sent, const float* __restrict__ emb) {
    size_t i = (size_t)blockIdx.x * blockDim.x + threadIdx.x;
    const size_t n = (size_t)TT * BBATCH * EE;
    if (i >= n) return;
    int e = i & (EE - 1);
    size_t r = i >> 9;
    int b = r & (BBATCH - 1);
    int t = (int)(r >> 6);
    g_ah[i] = __float2bfloat16(emb[(size_t)sent[b * TT + t] * EE + e]);
}

// fp32 -> bf16 (weights, one-time)
__global__ void cvt_bf16_kernel(const float* __restrict__ src,
                                __nv_bfloat16* __restrict__ dst, int n4) {
    int i = blockIdx.x * blockDim.x + threadIdx.x;
    if (i >= n4) return;
    float4 v = ((const float4*)src)[i];
    __nv_bfloat162 a, b;
    a.x = __float2bfloat16(v.x); a.y = __float2bfloat16(v.y);
    b.x = __float2bfloat16(v.z); b.y = __float2bfloat16(v.w);
    ((__nv_bfloat162*)dst)[2 * i] = a;
    ((__nv_bfloat162*)dst)[2 * i + 1] = b;
}

// ---------------- tensor-core GEMM (pure bf16, fp32 accum, cp.async) ----------------
__device__ __forceinline__ void ldsm4(uint32_t* r, uint32_t addr) {
    asm volatile("ldmatrix.sync.aligned.m8n8.x4.shared.b16 {%0,%1,%2,%3}, [%4];"
                 : "=r"(r[0]), "=r"(r[1]), "=r"(r[2]), "=r"(r[3]) : "r"(addr));
}
__device__ __forceinline__ void ldsm2(uint32_t* r, uint32_t addr) {
    asm volatile("ldmatrix.sync.aligned.m8n8.x2.shared.b16 {%0,%1}, [%2];"
                 : "=r"(r[0]), "=r"(r[1]) : "r"(addr));
}
__device__ __forceinline__ void mma_bf16(float* d, const uint32_t* a, const uint32_t* b) {
    asm volatile(
        "mma.sync.aligned.m16n8k16.row.col.f32.bf16.bf16.f32 "
        "{%0,%1,%2,%3}, {%4,%5,%6,%7}, {%8,%9}, {%0,%1,%2,%3};"
        : "+f"(d[0]), "+f"(d[1]), "+f"(d[2]), "+f"(d[3])
        : "r"(a[0]), "r"(a[1]), "r"(a[2]), "r"(a[3]), "r"(b[0]), "r"(b[1]));
}

#define KCHUNK 32
#define GLDK 40   // padded smem k-stride (80B): ldmatrix conflict-free

__global__ __launch_bounds__(256) void gemm_tc_kernel(
    const __nv_bfloat16* __restrict__ Ah,
    const __nv_bfloat16* __restrict__ Wh,
    const float* __restrict__ bias, float* __restrict__ C,
    int M, int N, int K)
{
    __shared__ __nv_bfloat16 sA[2][128][GLDK];
    __shared__ __nv_bfloat16 sW[2][128][GLDK];
    const int tid = threadIdx.x;
    const int bm = blockIdx.y * 128, bn = blockIdx.x * 128;
    const int row = tid >> 1, half = tid & 1;
    const int lane = tid & 31, wid = tid >> 5;
    const int wm = (wid >> 2) * 64, wn = (wid & 3) * 32;

    const __nv_bfloat16* gA = Ah + (size_t)(bm + row) * K + half * 16;
    const __nv_bfloat16* gW = Wh + (size_t)(bn + row) * K + half * 16;

    uint32_t aSt[2], wSt[2];
    aSt[0] = (uint32_t)__cvta_generic_to_shared(&sA[0][row][half * 16]);
    aSt[1] = (uint32_t)__cvta_generic_to_shared(&sA[1][row][half * 16]);
    wSt[0] = (uint32_t)__cvta_generic_to_shared(&sW[0][row][half * 16]);
    wSt[1] = (uint32_t)__cvta_generic_to_shared(&sW[1][row][half * 16]);

    float acc[4][4][4];
#pragma unroll
    for (int i = 0; i < 4; i++)
#pragma unroll
        for (int j = 0; j < 4; j++)
#pragma unroll
            for (int r = 0; r < 4; r++) acc[i][j][r] = 0.f;

    uint32_t aBase[2], wBase[2];
    {
        int ar = (lane & 15), ac = (lane >> 4) * 8;
        int wr = (lane & 7), wc = ((lane >> 3) & 1) * 8;
        aBase[0] = (uint32_t)__cvta_generic_to_shared(&sA[0][ar][ac]);
        aBase[1] = (uint32_t)__cvta_generic_to_shared(&sA[1][ar][ac]);
        wBase[0] = (uint32_t)__cvta_generic_to_shared(&sW[0][wr][wc]);
        wBase[1] = (uint32_t)__cvta_generic_to_shared(&sW[1][wr][wc]);
    }
    const uint32_t ROW16 = 16 * GLDK * 2;   // 1280 B
    const uint32_t ROW8  = 8 * GLDK * 2;    // 640 B

    CP_ASYNC16(aSt[0], gA);
    CP_ASYNC16(aSt[0] + 16, gA + 8);
    CP_ASYNC16(wSt[0], gW);
    CP_ASYNC16(wSt[0] + 16, gW + 8);
    CP_COMMIT();

    const int nk = K / KCHUNK;
    for (int ch = 0; ch < nk; ch++) {
        const int cur = ch & 1, nxt = cur ^ 1;
        if (ch + 1 < nk) {
            int k0 = (ch + 1) * KCHUNK;
            CP_ASYNC16(aSt[nxt], gA + k0);
            CP_ASYNC16(aSt[nxt] + 16, gA + k0 + 8);
            CP_ASYNC16(wSt[nxt], gW + k0);
            CP_ASYNC16(wSt[nxt] + 16, gW + k0 + 8);
            CP_COMMIT();
            CP_WAIT(1);
        } else {
            CP_WAIT(0);
        }
        __syncthreads();

#pragma unroll
        for (int ksub = 0; ksub < 2; ksub++) {
            uint32_t ah[4][4], wh[4][2];
            uint32_t aAddr = aBase[cur] + wm * (GLDK * 2) + ksub * 32;
            uint32_t wAddr = wBase[cur] + wn * (GLDK * 2) + ksub * 32;
#pragma unroll
            for (int mt = 0; mt < 4; mt++) ldsm4(ah[mt], aAddr + mt * ROW16);
#pragma unroll
            for (int nt = 0; nt < 4; nt++) ldsm2(wh[nt], wAddr + nt * ROW8);
#pragma unroll
            for (int mt = 0; mt < 4; mt++)
#pragma unroll
                for (int nt = 0; nt < 4; nt++)
                    mma_bf16(acc[mt][nt], ah[mt], wh[nt]);
        }
        __syncthreads();
    }

    const int g = lane >> 2, q = lane & 3;
#pragma unroll
    for (int mt = 0; mt < 4; mt++)
#pragma unroll
        for (int nt = 0; nt < 4; nt++) {
            int r0 = bm + wm + mt * 16 + g;
            int c0 = bn + wn + nt * 8 + q * 2;
            float b0v = bias[c0], b1v = bias[c0 + 1];
            float2 o0, o1;
            o0.x = acc[mt][nt][0] + b0v; o0.y = acc[mt][nt][1] + b1v;
            o1.x = acc[mt][nt][2] + b0v; o1.y = acc[mt][nt][3] + b1v;
            *(float2*)&C[(size_t)r0 * N + c0] = o0;
            *(float2*)&C[(size_t)(r0 + 8) * N + c0] = o1;
        }
}

// ---------------- persistent LSTM layer kernel ----------------
// grid = 128: d = bi>>6, bg = (bi>>3)&7, ugi = bi&7. block = 256 threads.
// W slice in registers; monotonic per-block release/acquire flags.
// h is staged into smem DUPLICATED as f32x2 pairs (pack2(h,h)) so the inner
// loop needs zero pack MOVs: 4 LDS.128 + 16 FFMA2 per k.
__global__ __launch_bounds__(256) void lstm_layer_kernel(
    const float* __restrict__ wt_l,   // g_wt + l*524288
    const float* __restrict__ pre,    // g_pre
    float* __restrict__ out,          // fp32 layer output (last layer only)
    __nv_bfloat16* __restrict__ outh, // bf16 A for next GEMM
    int wf32, unsigned int fbase)
{
    __shared__ ull hs2[2048];         // [k*8 + b] duplicated h pairs (16 KB)
    const int bi  = blockIdx.x;
    const int d   = bi >> 6;
    const int bg  = (bi >> 3) & 7;
    const int ugi = bi & 7;
    const int tid = threadIdx.x;
    const int w    = tid >> 5;
    const int lane = tid & 31;
    const int usub = lane & 3;
    const int kq   = lane >> 2;
    const int u_in = w * 4 + usub;
    const int u    = ugi * 32 + u_in;
    const int bglob = bg * 8 + kq;

    ull wif[32], wgo[32];
    {
        const float4* wb = (const float4*)(wt_l
            + (((size_t)(d * 8 + ugi) * 32 + u_in) * 1024) + kq * 128);
#pragma unroll
        for (int j = 0; j < 32; j++) {
            float4 v = wb[j];
            wif[j] = pack2(v.x, v.y);
            wgo[j] = pack2(v.z, v.w);
        }
    }

    unsigned int* flags = &g_flag2[d * 64 + bg * 8];
    float c = 0.f;

    for (int s = 0; s < TT; s++) {
        const int tt = d ? (TT - 1 - s) : s;
        const int rp = s & 1, wp = rp ^ 1;

        const float* prow = pre + ((size_t)tt * BBATCH + bglob) * 2048 + d * G4;
        float p0 = __ldg(prow + u);
        float p1 = __ldg(prow + 256 + u);
        float p2 = __ldg(prow + 512 + u);
        float p3 = __ldg(prow + 768 + u);

        if (s) {
            if (tid < 8) {
                const unsigned int* fp = flags + tid;
                const unsigned int target = fbase + (unsigned int)s;
                unsigned int v;
                do {
                    asm volatile("ld.acquire.gpu.global.u32 %0, [%1];"
                                 : "=r"(v) : "l"(fp) : "memory");
                } while (v < target);
            }
            __syncthreads();
        }

        // stage h (parity rp) into smem, duplicated into f32x2 pairs
        {
            const float4* hsrc = (const float4*)(g_hb + (((size_t)rp * 2 + d) * 8 + bg) * 2048);
#pragma unroll
            for (int i = tid; i < 512; i += 256) {
                float4 v = __ldcg(hsrc + i);
                ull* dst = hs2 + i * 4;
                dst[0] = pack2(v.x, v.x);
                dst[1] = pack2(v.y, v.y);
                dst[2] = pack2(v.z, v.z);
                dst[3] = pack2(v.w, v.w);
            }
        }
        __syncthreads();

        ull pif[8], pgo[8];
#pragma unroll
        for (int b2 = 0; b2 < 8; b2++) { pif[b2] = 0ull; pgo[b2] = 0ull; }
        const ull* hp = hs2 + kq * 256;   // 32 k x 8 b duplicated pairs
#pragma unroll
        for (int kk = 0; kk < 32; kk++) {
            ull hd[8];
            *(ulonglong2*)(hd)     = *(const ulonglong2*)(hp + kk * 8);
            *(ulonglong2*)(hd + 2) = *(const ulonglong2*)(hp + kk * 8 + 2);
            *(ulonglong2*)(hd + 4) = *(const ulonglong2*)(hp + kk * 8 + 4);
            *(ulonglong2*)(hd + 6) = *(const ulonglong2*)(hp + kk * 8 + 6);
#pragma unroll
            for (int b2 = 0; b2 < 8; b2++) {
                ffma2(pif[b2], hd[b2], wif[kk]);
                ffma2(pgo[b2], hd[b2], wgo[kk]);
            }
        }

#pragma unroll
        for (int rnd = 4; rnd <= 16; rnd <<= 1) {
#pragma unroll
            for (int b2 = 0; b2 < 8; b2++) {
                pif[b2] = addx2(pif[b2], __shfl_xor_sync(0xffffffffu, pif[b2], rnd));
                pgo[b2] = addx2(pgo[b2], __shfl_xor_sync(0xffffffffu, pgo[b2], rnd));
            }
        }

        ull q0 = (kq & 1) ? pif[1] : pif[0];
        ull q1 = (kq & 1) ? pif[3] : pif[2];
        ull q2 = (kq & 1) ? pif[5] : pif[4];
        ull q3 = (kq & 1) ? pif[7] : pif[6];
        ull r0 = (kq & 2) ? q1 : q0;
        ull r1 = (kq & 2) ? q3 : q2;
        ull sif = (kq & 4) ? r1 : r0;
        q0 = (kq & 1) ? pgo[1] : pgo[0];
        q1 = (kq & 1) ? pgo[3] : pgo[2];
        q2 = (kq & 1) ? pgo[5] : pgo[4];
        q3 = (kq & 1) ? pgo[7] : pgo[6];
        r0 = (kq & 2) ? q1 : q0;
        r1 = (kq & 2) ? q3 : q2;
        ull sgo = (kq & 4) ? r1 : r0;

        float gi, gf, gg, go;
        unpack2(gi, gf, sif);
        unpack2(gg, go, sgo);
        gi += p0; gf += p1; gg += p2; go += p3;

        float iv = 1.f / (1.f + expf(-gi));
        float fv = 1.f / (1.f + expf(-gf));
        float gv = tanhf(gg);
        float ov = 1.f / (1.f + expf(-go));
        c = fv * c + iv * gv;
        float h = ov * tanhf(c);

        // h for the next step (zeros at the final step => next layer's init state)
        float hstore = (s == TT - 1) ? 0.f : h;
        g_hb[(((size_t)wp * 2 + d) * 8 + bg) * 2048 + u_in * 8 + kq
             + (size_t)ugi * 256] = hstore;

        __syncthreads();
        if (tid == 0) {
            asm volatile("st.release.gpu.global.u32 [%0], %1;"
                         :: "l"(flags + ugi), "r"(fbase + (unsigned int)(s + 1)) : "memory");
        }

        // output stores AFTER the release — off the serial chain
        size_t oi = ((size_t)tt * BBATCH + bglob) * HD2 + d * HH + u;
        outh[oi] = __float2bfloat16(h);
        if (wf32) out[oi] = h;
    }
}

// ---------------- attention ----------------
__global__ __launch_bounds__(256) void energy_kernel(const float* __restrict__ z,
                                                     const float* __restrict__ aw2,
                                                     const float* __restrict__ ab2)
{
    int w = threadIdx.x >> 5, lane = threadIdx.x & 31;
    int r = blockIdx.x * 8 + w;
    const float* zr = z + (size_t)r * 512;
    float acc = 0.f;
#pragma unroll
    for (int j = 0; j < 16; j++) {
        int k = lane + j * 32;
        acc += tanhf(zr[k]) * aw2[k];
    }
#pragma unroll
    for (int o = 16; o > 0; o >>= 1) acc += __shfl_down_sync(0xffffffffu, acc, o);
    if (lane == 0) g_energy[r] = acc + ab2[0];
}

__global__ __launch_bounds__(256) void softmax_kernel() {
    __shared__ float red[256];
    int b = blockIdx.x, t = threadIdx.x;
    float e = g_energy[t * 64 + b];
    red[t] = e;
    __syncthreads();
    for (int s = 128; s > 0; s >>= 1) {
        if (t < s) red[t] = fmaxf(red[t], red[t + s]);
        __syncthreads();
    }
    float m = red[0];
    __syncthreads();
    float p = expf(e - m);
    red[t] = p;
    __syncthreads();
    for (int s = 128; s > 0; s >>= 1) {
        if (t < s) red[t] += red[t + s];
        __syncthreads();
    }
    g_energy[t * 64 + b] = p / red[0];
}

__global__ __launch_bounds__(256) void feats_kernel(const float* __restrict__ y,
                                                    const float* __restrict__ hw,
                                                    const float* __restrict__ hb)
{
    int w = threadIdx.x >> 5, lane = threadIdx.x & 31;
    int r = blockIdx.x * 8 + w;
    const float* yr = y + (size_t)r * 512;
    float acc[NTAGS];
#pragma unroll
    for (int i = 0; i < NTAGS; i++) acc[i] = 0.f;
#pragma unroll
    for (int j = 0; j < 16; j++) {
        int k = lane + j * 32;
        float v = yr[k];
#pragma unroll
        for (int i = 0; i < NTAGS; i++) acc[i] += v * hw[i * 512 + k];
    }
#pragma unroll
    for (int i = 0; i < NTAGS; i++)
#pragma unroll
        for (int o = 16; o > 0; o >>= 1) acc[i] += __shfl_down_sync(0xffffffffu, acc[i], o);
    if (lane == 0) {
        float wt = 1.f + g_energy[r];
        int b = r & 63, t = r >> 6;
#pragma unroll
        for (int i = 0; i < NTAGS; i++)
            g_feats[((size_t)b * TT + t) * NTAGS + i] = wt * acc[i] + hb[i];
    }
}

// ---------------- CRF ----------------
__global__ __launch_bounds__(32) void crf_kernel(const int* __restrict__ tags,
                                                 const float* __restrict__ mask,
                                                 const float* __restrict__ trans,
                                                 float* __restrict__ out)
{
    __shared__ float tr[36];
    int b = blockIdx.x, lid = threadIdx.x;
    for (int i = lid; i < 36; i += 32) tr[i] = trans[i];
    __syncwarp();

    const int ii = lid % NTAGS;
    const float* fb = g_feats + (size_t)b * TT * NTAGS;
    const float* mb = mask + (size_t)b * TT;

    float fv = (ii == TAG_START) ? 0.f : NEGV;
    for (int t = 0; t < TT; t++) {
        float fj[NTAGS];
#pragma unroll
        for (int j = 0; j < NTAGS; j++) fj[j] = __shfl_sync(0xffffffffu, fv, j);
        float v[NTAGS];
        float m = -3.4e38f;
#pragma unroll
        for (int j = 0; j < NTAGS; j++) {
            v[j] = fj[j] + tr[ii * NTAGS + j];
            m = fmaxf(m, v[j]);
        }
        float ssum = 0.f;
#pragma unroll
        for (int j = 0; j < NTAGS; j++) ssum += expf(v[j] - m);
        float nxt = m + logf(ssum) + fb[t * NTAGS + ii];
        fv = (mb[t] > 0.f) ? nxt : fv;
    }
    float sv = fv + tr[TAG_STOP * NTAGS + ii];
    float gvals[NTAGS];
#pragma unroll
    for (int j = 0; j < NTAGS; j++) gvals[j] = __shfl_sync(0xffffffffu, sv, j);
    float m2 = -3.4e38f;
#pragma unroll
    for (int j = 0; j < NTAGS; j++) m2 = fmaxf(m2, gvals[j]);
    float s2 = 0.f;
#pragma unroll
    for (int j = 0; j < NTAGS; j++) s2 += expf(gvals[j] - m2);
    float fwd = m2 + logf(s2);

    float gold = 0.f, msum = 0.f;
    for (int t = lid; t < TT; t += 32) {
        int cur = tags[b * TT + t];
        int prev = t ? tags[b * TT + t - 1] : TAG_START;
        float mm = mb[t];
        gold += (fb[t * NTAGS + cur] + tr[cur * NTAGS + prev]) * mm;
        msum += mm;
    }
#pragma unroll
    for (int o = 16; o > 0; o >>= 1) {
        gold += __shfl_down_sync(0xffffffffu, gold, o);
        msum += __shfl_down_sync(0xffffffffu, msum, o);
    }
    if (lid == 0) {
        int sl = (int)(msum + 0.5f);
        int last = (sl > 0) ? tags[b * TT + sl - 1] : TAG_START;
        gold += tr[TAG_STOP * NTAGS + last];
        atomicAdd(out, (fwd - gold) * (1.f / 64.f));
    }
}

// ---------------- launch ----------------
extern "C" void kernel_launch(void* const* d_in, const int* in_sizes, int n_in,
                              void* d_out, int out_size)
{
    const int*   sentences = (const int*)d_in[0];
    const int*   tags      = (const int*)d_in[1];
    const float* mask      = (const float*)d_in[2];
    const float* embed     = (const float*)d_in[3];
    const float* w_ih      = (const float*)d_in[4];
    const float* w_hh      = (const float*)d_in[5];
    const float* b_ih      = (const float*)d_in[6];
    const float* b_hh      = (const float*)d_in[7];
    const float* aw1       = (const float*)d_in[8];
    const float* ab1       = (const float*)d_in[9];
    const float* aw2       = (const float*)d_in[10];
    const float* ab2       = (const float*)d_in[11];
    const float* hw        = (const float*)d_in[12];
    const float* hb        = (const float*)d_in[13];
    const float* trans     = (const float*)d_in[14];
    float* out = (float*)d_out;

    zero_out_kernel<<<1, 1>>>(out);
    bias_kernel<<<24, 256>>>(b_ih, b_hh);
    wt_kernel<<<6144, 256>>>(w_hh);
    embed_kernel<<<32768, 256>>>(sentences, embed);
    zero_state_kernel<<<256, 256>>>();   // once: g_hb parity buffers + flags

    float *px, *py, *ppre, *pbias, *pwt;
    __nv_bfloat16 *pah, *pwh2;
    cudaGetSymbolAddress((void**)&px, g_x);
    cudaGetSymbolAddress((void**)&py, g_y);
    cudaGetSymbolAddress((void**)&ppre, g_pre);
    cudaGetSymbolAddress((void**)&pbias, g_bias);
    cudaGetSymbolAddress((void**)&pwt, g_wt);
    cudaGetSymbolAddress((void**)&pah, g_ah);
    cudaGetSymbolAddress((void**)&pwh2, g_wh2);

    const int M = TT * BBATCH;        // 16384
    const int NWIH = 3 * 2 * G4 * EE; // 3145728

    cvt_bf16_kernel<<<NWIH / 4 / 256, 256>>>(w_ih, pwh2, NWIH / 4);
    cvt_bf16_kernel<<<512 * 512 / 4 / 256, 256>>>(aw1, pwh2 + NWIH, 512 * 512 / 4);

    for (int l = 0; l < 3; l++) {
        dim3 g1(2048 / 128, M / 128);
        gemm_tc_kernel<<<g1, 256>>>(pah,
                                    pwh2 + (size_t)l * 2 * G4 * EE,
                                    pbias + l * 2048, ppre, M, 2048, EE);
        const float* wtl = pwt + (size_t)l * 2 * 8 * 32768;
        lstm_layer_kernel<<<128, 256>>>(wtl, ppre, py, pah, (l == 2) ? 1 : 0,
                                        (unsigned int)(l * 256));
    }
    float* lstm_out = py;
    float* zbuf = px;

    dim3 g2(512 / 128, M / 128);
    gemm_tc_kernel<<<g2, 256>>>(pah, pwh2 + NWIH, ab1, zbuf, M, 512, EE);
    energy_kernel<<<M / 8, 256>>>(zbuf, aw2, ab2);
    softmax_kernel<<<BBATCH, 256>>>();
    feats_kernel<<<M / 8, 256>>>(lstm_out, hw, hb);
    crf_kernel<<<BBATCH, 32>>>(tags, mask, trans, out);
}

// round 15
// speedup vs baseline: 1.4449x; 1.4449x over previous
#include <cuda_runtime.h>
#include <cuda_bf16.h>
#include <math.h>
#include <stdint.h>

// Problem constants
#define TT 256      // T
#define BBATCH 64   // B
#define EE 512      // E (= input dim for ALL layers, since 2H = 512)
#define HH 256      // H
#define G4 1024     // 4H
#define HD2 512     // 2H
#define NTAGS 6
#define TAG_START 4
#define TAG_STOP 5
#define NEGV -1000000.0f

typedef unsigned long long ull;

// ---------------- device scratch (static allocations only) ----------------
__device__ float g_x[(size_t)TT * BBATCH * EE];            // zbuf (attention)
__device__ float g_pre[(size_t)TT * BBATCH * 2048];        // (t,b,[dir0 1024 | dir1 1024])
__device__ float g_hb[2 * 2 * 8 * 2048];                   // [parity][dir][bg][u*8+b] h-state
__device__ float g_bias[3 * 2 * G4];                       // b_ih + b_hh combined
__device__ float g_wt[(size_t)3 * 2 * 8 * 32768];          // w_hh re-tiled per (l,d,ugi,u_in,kq,kk,g)
__device__ float g_energy[(size_t)TT * BBATCH];            // energy then softmax weights
__device__ float g_feats[(size_t)BBATCH * TT * NTAGS];     // [b][t][tag]
__device__ unsigned int g_flag2[128];                      // [d*64 + bg*8 + ugi] monotonic step flags
// bf16 buffers for tensor-core GEMM (A produced by embed / LSTM; also lstm_out for feats)
__device__ __nv_bfloat16 g_ah[(size_t)TT * BBATCH * EE];   // A (bf16)
#define WSPLIT_N (3 * 2 * G4 * EE + 512 * 512)             // w_ih (all) + aw1
__device__ __nv_bfloat16 g_wh2[WSPLIT_N];

// ---------------- f32x2 packed-FMA helpers ----------------
__device__ __forceinline__ void ffma2(ull& d, ull a, ull b) {
    asm("fma.rn.f32x2 %0, %1, %2, %0;" : "+l"(d) : "l"(a), "l"(b));
}
__device__ __forceinline__ ull addx2(ull a, ull b) {
    ull r;
    asm("add.rn.f32x2 %0, %1, %2;" : "=l"(r) : "l"(a), "l"(b));
    return r;
}
__device__ __forceinline__ ull pack2(float x, float y) {
    ull r;
    asm("mov.b64 %0, {%1, %2};" : "=l"(r) : "f"(x), "f"(y));
    return r;
}
__device__ __forceinline__ void unpack2(float& x, float& y, ull v) {
    asm("mov.b64 {%0, %1}, %2;" : "=f"(x), "=f"(y) : "l"(v));
}

// ---------------- cp.async helpers ----------------
#define CP_ASYNC16(dst, src) \
    asm volatile("cp.async.cg.shared.global [%0], [%1], 16;" :: "r"(dst), "l"(src))
#define CP_COMMIT() asm volatile("cp.async.commit_group;" ::: "memory")
#define CP_WAIT(n) asm volatile("cp.async.wait_group %0;" :: "n"(n) : "memory")

// ---------------- init kernel (merged prologue) ----------------
__global__ void init_kernel(float* out, const float* __restrict__ b_ih,
                            const float* __restrict__ b_hh) {
    int i = blockIdx.x * blockDim.x + threadIdx.x;
    if (i == 0) out[0] = 0.f;
    if (i < 3 * 2 * G4) g_bias[i] = b_ih[i] + b_hh[i];
    if (i < 2 * 2 * 8 * 2048) g_hb[i] = 0.f;
    if (i < 128) g_flag2[i] = 0u;
}

// Re-tile w_hh (3,2,1024,256) into g_wt[l][d][ugi][u_in][kq][kk][g]
__global__ void wt_kernel(const float* __restrict__ whh) {
    size_t i = (size_t)blockIdx.x * blockDim.x + threadIdx.x;
    const size_t n = (size_t)3 * 2 * 8 * 32768;
    if (i >= n) return;
    int g    = i & 3;
    int kk   = (i >> 2) & 31;
    int kq   = (i >> 7) & 7;
    int u_in = (i >> 10) & 31;
    int ugi  = (i >> 15) & 7;
    int ld   = (int)(i >> 18);
    int u = ugi * 32 + u_in;
    int k = kq * 32 + kk;
    g_wt[i] = whh[((size_t)ld * G4 + g * 256 + u) * HH + k];
}

// gather embeddings -> g_ah[t][b][e] (bf16)
__global__ void embed_kernel(const int* __restrict__ sent, const float* __restrict__ emb) {
    size_t i = (size_t)blockIdx.x * blockDim.x + threadIdx.x;
    const size_t n = (size_t)TT * BBATCH * EE;
    if (i >= n) return;
    int e = i & (EE - 1);
    size_t r = i >> 9;
    int b = r & (BBATCH - 1);
    int t = (int)(r >> 6);
    g_ah[i] = __float2bfloat16(emb[(size_t)sent[b * TT + t] * EE + e]);
}

// fp32 -> bf16 (weights, one-time)
__global__ void cvt_bf16_kernel(const float* __restrict__ src,
                                __nv_bfloat16* __restrict__ dst, int n4) {
    int i = blockIdx.x * blockDim.x + threadIdx.x;
    if (i >= n4) return;
    float4 v = ((const float4*)src)[i];
    __nv_bfloat162 a, b;
    a.x = __float2bfloat16(v.x); a.y = __float2bfloat16(v.y);
    b.x = __float2bfloat16(v.z); b.y = __float2bfloat16(v.w);
    ((__nv_bfloat162*)dst)[2 * i] = a;
    ((__nv_bfloat162*)dst)[2 * i + 1] = b;
}

// ---------------- tensor-core GEMM (pure bf16, fp32 accum, cp.async) — R11 proven ----
__device__ __forceinline__ void ldsm4(uint32_t* r, uint32_t addr) {
    asm volatile("ldmatrix.sync.aligned.m8n8.x4.shared.b16 {%0,%1,%2,%3}, [%4];"
                 : "=r"(r[0]), "=r"(r[1]), "=r"(r[2]), "=r"(r[3]) : "r"(addr));
}
__device__ __forceinline__ void ldsm2(uint32_t* r, uint32_t addr) {
    asm volatile("ldmatrix.sync.aligned.m8n8.x2.shared.b16 {%0,%1}, [%2];"
                 : "=r"(r[0]), "=r"(r[1]) : "r"(addr));
}
__device__ __forceinline__ void mma_bf16(float* d, const uint32_t* a, const uint32_t* b) {
    asm volatile(
        "mma.sync.aligned.m16n8k16.row.col.f32.bf16.bf16.f32 "
        "{%0,%1,%2,%3}, {%4,%5,%6,%7}, {%8,%9}, {%0,%1,%2,%3};"
        : "+f"(d[0]), "+f"(d[1]), "+f"(d[2]), "+f"(d[3])
        : "r"(a[0]), "r"(a[1]), "r"(a[2]), "r"(a[3]), "r"(b[0]), "r"(b[1]));
}

#define KCHUNK 32
#define GLDK 40   // padded smem k-stride (80B): ldmatrix conflict-free

__global__ __launch_bounds__(256) void gemm_tc_kernel(
    const __nv_bfloat16* __restrict__ Ah,
    const __nv_bfloat16* __restrict__ Wh,
    const float* __restrict__ bias, float* __restrict__ C,
    int M, int N, int K)
{
    __shared__ __nv_bfloat16 sA[2][128][GLDK];
    __shared__ __nv_bfloat16 sW[2][128][GLDK];
    const int tid = threadIdx.x;
    const int bm = blockIdx.y * 128, bn = blockIdx.x * 128;
    const int row = tid >> 1, half = tid & 1;
    const int lane = tid & 31, wid = tid >> 5;
    const int wm = (wid >> 2) * 64, wn = (wid & 3) * 32;

    const __nv_bfloat16* gA = Ah + (size_t)(bm + row) * K + half * 16;
    const __nv_bfloat16* gW = Wh + (size_t)(bn + row) * K + half * 16;

    uint32_t aSt[2], wSt[2];
    aSt[0] = (uint32_t)__cvta_generic_to_shared(&sA[0][row][half * 16]);
    aSt[1] = (uint32_t)__cvta_generic_to_shared(&sA[1][row][half * 16]);
    wSt[0] = (uint32_t)__cvta_generic_to_shared(&sW[0][row][half * 16]);
    wSt[1] = (uint32_t)__cvta_generic_to_shared(&sW[1][row][half * 16]);

    float acc[4][4][4];
#pragma unroll
    for (int i = 0; i < 4; i++)
#pragma unroll
        for (int j = 0; j < 4; j++)
#pragma unroll
            for (int r = 0; r < 4; r++) acc[i][j][r] = 0.f;

    uint32_t aBase[2], wBase[2];
    {
        int ar = (lane & 15), ac = (lane >> 4) * 8;
        int wr = (lane & 7), wc = ((lane >> 3) & 1) * 8;
        aBase[0] = (uint32_t)__cvta_generic_to_shared(&sA[0][ar][ac]);
        aBase[1] = (uint32_t)__cvta_generic_to_shared(&sA[1][ar][ac]);
        wBase[0] = (uint32_t)__cvta_generic_to_shared(&sW[0][wr][wc]);
        wBase[1] = (uint32_t)__cvta_generic_to_shared(&sW[1][wr][wc]);
    }
    const uint32_t ROW16 = 16 * GLDK * 2;   // 1280 B
    const uint32_t ROW8  = 8 * GLDK * 2;    // 640 B

    CP_ASYNC16(aSt[0], gA);
    CP_ASYNC16(aSt[0] + 16, gA + 8);
    CP_ASYNC16(wSt[0], gW);
    CP_ASYNC16(wSt[0] + 16, gW + 8);
    CP_COMMIT();

    const int nk = K / KCHUNK;
    for (int ch = 0; ch < nk; ch++) {
        const int cur = ch & 1, nxt = cur ^ 1;
        if (ch + 1 < nk) {
            int k0 = (ch + 1) * KCHUNK;
            CP_ASYNC16(aSt[nxt], gA + k0);
            CP_ASYNC16(aSt[nxt] + 16, gA + k0 + 8);
            CP_ASYNC16(wSt[nxt], gW + k0);
            CP_ASYNC16(wSt[nxt] + 16, gW + k0 + 8);
            CP_COMMIT();
            CP_WAIT(1);
        } else {
            CP_WAIT(0);
        }
        __syncthreads();

#pragma unroll
        for (int ksub = 0; ksub < 2; ksub++) {
            uint32_t ah[4][4], wh[4][2];
            uint32_t aAddr = aBase[cur] + wm * (GLDK * 2) + ksub * 32;
            uint32_t wAddr = wBase[cur] + wn * (GLDK * 2) + ksub * 32;
#pragma unroll
            for (int mt = 0; mt < 4; mt++) ldsm4(ah[mt], aAddr + mt * ROW16);
#pragma unroll
            for (int nt = 0; nt < 4; nt++) ldsm2(wh[nt], wAddr + nt * ROW8);
#pragma unroll
            for (int mt = 0; mt < 4; mt++)
#pragma unroll
                for (int nt = 0; nt < 4; nt++)
                    mma_bf16(acc[mt][nt], ah[mt], wh[nt]);
        }
        __syncthreads();
    }

    const int g = lane >> 2, q = lane & 3;
#pragma unroll
    for (int mt = 0; mt < 4; mt++)
#pragma unroll
        for (int nt = 0; nt < 4; nt++) {
            int r0 = bm + wm + mt * 16 + g;
            int c0 = bn + wn + nt * 8 + q * 2;
            float b0v = bias[c0], b1v = bias[c0 + 1];
            float2 o0, o1;
            o0.x = acc[mt][nt][0] + b0v; o0.y = acc[mt][nt][1] + b1v;
            o1.x = acc[mt][nt][2] + b0v; o1.y = acc[mt][nt][3] + b1v;
            *(float2*)&C[(size_t)r0 * N + c0] = o0;
            *(float2*)&C[(size_t)(r0 + 8) * N + c0] = o1;
        }
}

// ---------------- persistent LSTM layer kernel (R11 proven, fp32 out removed) ----
// grid = 128: d = bi>>6, bg = (bi>>3)&7, ugi = bi&7. block = 256 threads.
// W slice in registers; monotonic per-block release/acquire flags; h staged
// into smem cooperatively (fp32, deduped); outputs (bf16 only) stored after
// the release flag, off the serial chain.
__global__ __launch_bounds__(256) void lstm_layer_kernel(
    const float* __restrict__ wt_l,   // g_wt + l*524288
    const float* __restrict__ pre,    // g_pre
    __nv_bfloat16* __restrict__ outh, // bf16 layer output (= next GEMM's A)
    unsigned int fbase)
{
    __shared__ float hs[2048];
    const int bi  = blockIdx.x;
    const int d   = bi >> 6;
    const int bg  = (bi >> 3) & 7;
    const int ugi = bi & 7;
    const int tid = threadIdx.x;
    const int w    = tid >> 5;
    const int lane = tid & 31;
    const int usub = lane & 3;
    const int kq   = lane >> 2;
    const int u_in = w * 4 + usub;
    const int u    = ugi * 32 + u_in;
    const int bglob = bg * 8 + kq;

    ull wif[32], wgo[32];
    {
        const float4* wb = (const float4*)(wt_l
            + (((size_t)(d * 8 + ugi) * 32 + u_in) * 1024) + kq * 128);
#pragma unroll
        for (int j = 0; j < 32; j++) {
            float4 v = wb[j];
            wif[j] = pack2(v.x, v.y);
            wgo[j] = pack2(v.z, v.w);
        }
    }

    unsigned int* flags = &g_flag2[d * 64 + bg * 8];
    float c = 0.f;

    for (int s = 0; s < TT; s++) {
        const int tt = d ? (TT - 1 - s) : s;
        const int rp = s & 1, wp = rp ^ 1;

        const float* prow = pre + ((size_t)tt * BBATCH + bglob) * 2048 + d * G4;
        float p0 = __ldg(prow + u);
        float p1 = __ldg(prow + 256 + u);
        float p2 = __ldg(prow + 512 + u);
        float p3 = __ldg(prow + 768 + u);

        if (s) {
            if (tid < 8) {
                const unsigned int* fp = flags + tid;
                const unsigned int target = fbase + (unsigned int)s;
                unsigned int v;
                do {
                    asm volatile("ld.acquire.gpu.global.u32 %0, [%1];"
                                 : "=r"(v) : "l"(fp) : "memory");
                } while (v < target);
            }
            __syncthreads();
        }

        {
            const float4* hsrc = (const float4*)(g_hb + (((size_t)rp * 2 + d) * 8 + bg) * 2048);
#pragma unroll
            for (int i = tid; i < 512; i += 256) ((float4*)hs)[i] = __ldcg(hsrc + i);
        }
        __syncthreads();

        ull pif[8], pgo[8];
#pragma unroll
        for (int b2 = 0; b2 < 8; b2++) { pif[b2] = 0ull; pgo[b2] = 0ull; }
        const float* hp = hs + kq * 256;
#pragma unroll
        for (int kk = 0; kk < 32; kk++) {
            float hv[8];
            *(float4*)hv       = *(const float4*)(hp + kk * 8);
            *(float4*)(hv + 4) = *(const float4*)(hp + kk * 8 + 4);
#pragma unroll
            for (int b2 = 0; b2 < 8; b2++) {
                ull hh = pack2(hv[b2], hv[b2]);
                ffma2(pif[b2], hh, wif[kk]);
                ffma2(pgo[b2], hh, wgo[kk]);
            }
        }

#pragma unroll
        for (int rnd = 4; rnd <= 16; rnd <<= 1) {
#pragma unroll
            for (int b2 = 0; b2 < 8; b2++) {
                pif[b2] = addx2(pif[b2], __shfl_xor_sync(0xffffffffu, pif[b2], rnd));
                pgo[b2] = addx2(pgo[b2], __shfl_xor_sync(0xffffffffu, pgo[b2], rnd));
            }
        }

        ull q0 = (kq & 1) ? pif[1] : pif[0];
        ull q1 = (kq & 1) ? pif[3] : pif[2];
        ull q2 = (kq & 1) ? pif[5] : pif[4];
        ull q3 = (kq & 1) ? pif[7] : pif[6];
        ull r0 = (kq & 2) ? q1 : q0;
        ull r1 = (kq & 2) ? q3 : q2;
        ull sif = (kq & 4) ? r1 : r0;
        q0 = (kq & 1) ? pgo[1] : pgo[0];
        q1 = (kq & 1) ? pgo[3] : pgo[2];
        q2 = (kq & 1) ? pgo[5] : pgo[4];
        q3 = (kq & 1) ? pgo[7] : pgo[6];
        r0 = (kq & 2) ? q1 : q0;
        r1 = (kq & 2) ? q3 : q2;
        ull sgo = (kq & 4) ? r1 : r0;

        float gi, gf, gg, go;
        unpack2(gi, gf, sif);
        unpack2(gg, go, sgo);
        gi += p0; gf += p1; gg += p2; go += p3;

        float iv = 1.f / (1.f + expf(-gi));
        float fv = 1.f / (1.f + expf(-gf));
        float gv = tanhf(gg);
        float ov = 1.f / (1.f + expf(-go));
        c = fv * c + iv * gv;
        float h = ov * tanhf(c);

        // h for the next step (zeros at the final step => next layer's init state)
        float hstore = (s == TT - 1) ? 0.f : h;
        g_hb[(((size_t)wp * 2 + d) * 8 + bg) * 2048 + u_in * 8 + kq
             + (size_t)ugi * 256] = hstore;

        __syncthreads();
        if (tid == 0) {
            asm volatile("st.release.gpu.global.u32 [%0], %1;"
                         :: "l"(flags + ugi), "r"(fbase + (unsigned int)(s + 1)) : "memory");
        }

        // output store AFTER the release — off the serial chain
        size_t oi = ((size_t)tt * BBATCH + bglob) * HD2 + d * HH + u;
        outh[oi] = __float2bfloat16(h);
    }
}

// ---------------- attention ----------------
__global__ __launch_bounds__(256) void energy_kernel(const float* __restrict__ z,
                                                     const float* __restrict__ aw2,
                                                     const float* __restrict__ ab2)
{
    int w = threadIdx.x >> 5, lane = threadIdx.x & 31;
    int r = blockIdx.x * 8 + w;
    const float* zr = z + (size_t)r * 512;
    float acc = 0.f;
#pragma unroll
    for (int j = 0; j < 16; j++) {
        int k = lane + j * 32;
        acc += tanhf(zr[k]) * aw2[k];
    }
#pragma unroll
    for (int o = 16; o > 0; o >>= 1) acc += __shfl_down_sync(0xffffffffu, acc, o);
    if (lane == 0) g_energy[r] = acc + ab2[0];
}

__global__ __launch_bounds__(256) void softmax_kernel() {
    __shared__ float red[256];
    int b = blockIdx.x, t = threadIdx.x;
    float e = g_energy[t * 64 + b];
    red[t] = e;
    __syncthreads();
    for (int s = 128; s > 0; s >>= 1) {
        if (t < s) red[t] = fmaxf(red[t], red[t + s]);
        __syncthreads();
    }
    float m = red[0];
    __syncthreads();
    float p = expf(e - m);
    red[t] = p;
    __syncthreads();
    for (int s = 128; s > 0; s >>= 1) {
        if (t < s) red[t] += red[t + s];
        __syncthreads();
    }
    g_energy[t * 64 + b] = p / red[0];
}

// feats from bf16 lstm_out (same data the attention GEMM consumes)
__global__ __launch_bounds__(256) void feats_kernel(const __nv_bfloat16* __restrict__ y,
                                                    const float* __restrict__ hw,
                                                    const float* __restrict__ hb)
{
    int w = threadIdx.x >> 5, lane = threadIdx.x & 31;
    int r = blockIdx.x * 8 + w;
    const __nv_bfloat16* yr = y + (size_t)r * 512;
    float acc[NTAGS];
#pragma unroll
    for (int i = 0; i < NTAGS; i++) acc[i] = 0.f;
#pragma unroll
    for (int j = 0; j < 16; j++) {
        int k = lane + j * 32;
        float v = __bfloat162float(yr[k]);
#pragma unroll
        for (int i = 0; i < NTAGS; i++) acc[i] += v * hw[i * 512 + k];
    }
#pragma unroll
    for (int i = 0; i < NTAGS; i++)
#pragma unroll
        for (int o = 16; o > 0; o >>= 1) acc[i] += __shfl_down_sync(0xffffffffu, acc[i], o);
    if (lane == 0) {
        float wt = 1.f + g_energy[r];
        int b = r & 63, t = r >> 6;
#pragma unroll
        for (int i = 0; i < NTAGS; i++)
            g_feats[((size_t)b * TT + t) * NTAGS + i] = wt * acc[i] + hb[i];
    }
}

// ---------------- CRF ----------------
__global__ __launch_bounds__(32) void crf_kernel(const int* __restrict__ tags,
                                                 const float* __restrict__ mask,
                                                 const float* __restrict__ trans,
                                                 float* __restrict__ out)
{
    __shared__ float tr[36];
    int b = blockIdx.x, lid = threadIdx.x;
    for (int i = lid; i < 36; i += 32) tr[i] = trans[i];
    __syncwarp();

    const int ii = lid % NTAGS;
    const float* fb = g_feats + (size_t)b * TT * NTAGS;
    const float* mb = mask + (size_t)b * TT;

    float fv = (ii == TAG_START) ? 0.f : NEGV;
    for (int t = 0; t < TT; t++) {
        float fj[NTAGS];
#pragma unroll
        for (int j = 0; j < NTAGS; j++) fj[j] = __shfl_sync(0xffffffffu, fv, j);
        float v[NTAGS];
        float m = -3.4e38f;
#pragma unroll
        for (int j = 0; j < NTAGS; j++) {
            v[j] = fj[j] + tr[ii * NTAGS + j];
            m = fmaxf(m, v[j]);
        }
        float ssum = 0.f;
#pragma unroll
        for (int j = 0; j < NTAGS; j++) ssum += expf(v[j] - m);
        float nxt = m + logf(ssum) + fb[t * NTAGS + ii];
        fv = (mb[t] > 0.f) ? nxt : fv;
    }
    float sv = fv + tr[TAG_STOP * NTAGS + ii];
    float gvals[NTAGS];
#pragma unroll
    for (int j = 0; j < NTAGS; j++) gvals[j] = __shfl_sync(0xffffffffu, sv, j);
    float m2 = -3.4e38f;
#pragma unroll
    for (int j = 0; j < NTAGS; j++) m2 = fmaxf(m2, gvals[j]);
    float s2 = 0.f;
#pragma unroll
    for (int j = 0; j < NTAGS; j++) s2 += expf(gvals[j] - m2);
    float fwd = m2 + logf(s2);

    float gold = 0.f, msum = 0.f;
    for (int t = lid; t < TT; t += 32) {
        int cur = tags[b * TT + t];
        int prev = t ? tags[b * TT + t - 1] : TAG_START;
        float mm = mb[t];
        gold += (fb[t * NTAGS + cur] + tr[cur * NTAGS + prev]) * mm;
        msum += mm;
    }
#pragma unroll
    for (int o = 16; o > 0; o >>= 1) {
        gold += __shfl_down_sync(0xffffffffu, gold, o);
        msum += __shfl_down_sync(0xffffffffu, msum, o);
    }
    if (lid == 0) {
        int sl = (int)(msum + 0.5f);
        int last = (sl > 0) ? tags[b * TT + sl - 1] : TAG_START;
        gold += tr[TAG_STOP * NTAGS + last];
        atomicAdd(out, (fwd - gold) * (1.f / 64.f));
    }
}

// ---------------- launch ----------------
extern "C" void kernel_launch(void* const* d_in, const int* in_sizes, int n_in,
                              void* d_out, int out_size)
{
    const int*   sentences = (const int*)d_in[0];
    const int*   tags      = (const int*)d_in[1];
    const float* mask      = (const float*)d_in[2];
    const float* embed     = (const float*)d_in[3];
    const float* w_ih      = (const float*)d_in[4];
    const float* w_hh      = (const float*)d_in[5];
    const float* b_ih      = (const float*)d_in[6];
    const float* b_hh      = (const float*)d_in[7];
    const float* aw1       = (const float*)d_in[8];
    const float* ab1       = (const float*)d_in[9];
    const float* aw2       = (const float*)d_in[10];
    const float* ab2       = (const float*)d_in[11];
    const float* hw        = (const float*)d_in[12];
    const float* hb        = (const float*)d_in[13];
    const float* trans     = (const float*)d_in[14];
    float* out = (float*)d_out;

    init_kernel<<<256, 256>>>(out, b_ih, b_hh);
    wt_kernel<<<6144, 256>>>(w_hh);
    embed_kernel<<<32768, 256>>>(sentences, embed);

    float *px, *ppre, *pbias, *pwt;
    __nv_bfloat16 *pah, *pwh2;
    cudaGetSymbolAddress((void**)&px, g_x);
    cudaGetSymbolAddress((void**)&ppre, g_pre);
    cudaGetSymbolAddress((void**)&pbias, g_bias);
    cudaGetSymbolAddress((void**)&pwt, g_wt);
    cudaGetSymbolAddress((void**)&pah, g_ah);
    cudaGetSymbolAddress((void**)&pwh2, g_wh2);

    const int M = TT * BBATCH;        // 16384
    const int NWIH = 3 * 2 * G4 * EE; // 3145728

    cvt_bf16_kernel<<<NWIH / 4 / 256, 256>>>(w_ih, pwh2, NWIH / 4);
    cvt_bf16_kernel<<<512 * 512 / 4 / 256, 256>>>(aw1, pwh2 + NWIH, 512 * 512 / 4);

    for (int l = 0; l < 3; l++) {
        dim3 g1(2048 / 128, M / 128);
        gemm_tc_kernel<<<g1, 256>>>(pah,
                                    pwh2 + (size_t)l * 2 * G4 * EE,
                                    pbias + l * 2048, ppre, M, 2048, EE);
        const float* wtl = pwt + (size_t)l * 2 * 8 * 32768;
        lstm_layer_kernel<<<128, 256>>>(wtl, ppre, pah, (unsigned int)(l * 256));
    }
    float* zbuf = px;

    dim3 g2(512 / 128, M / 128);
    gemm_tc_kernel<<<g2, 256>>>(pah, pwh2 + NWIH, ab1, zbuf, M, 512, EE);
    energy_kernel<<<M / 8, 256>>>(zbuf, aw2, ab2);
    softmax_kernel<<<BBATCH, 256>>>();
    feats_kernel<<<M / 8, 256>>>(pah, hw, hb);
    crf_kernel<<<BBATCH, 32>>>(tags, mask, trans, out);
}